// round 2
// baseline (speedup 1.0000x reference)
#include <cuda_runtime.h>
#include <cuda_bf16.h>
#include <math.h>

// Problem constants (fixed by the reference)
#define GROUPS 8
#define DG     32        // D / GROUPS
#define W_DIM  512
#define D_DIM  256
#define KCOEF  9         // CHEB_DEG + 1
#define RANK   16
#define DT_C   0.1f
// 16 W-elements per lane (512 / 32)
#define WPL    16

// Precomputed per-group integration matrix M_g = (I + dt A + 0.5 dt^2 A^2)^4
__device__ float d_M[GROUPS * DG * DG];

// ---------------------------------------------------------------------------
// Precompute kernel: one block per group, 1024 threads (i = tid>>5, j = tid&31)
// ---------------------------------------------------------------------------
__global__ void precompute_M_kernel(const float* __restrict__ U,
                                    const float* __restrict__ V,
                                    const float* __restrict__ S) {
    const int g   = blockIdx.x;
    const int tid = threadIdx.x;
    const int i   = tid >> 5;
    const int j   = tid & 31;

    __shared__ float Us[DG * RANK], Vs[DG * RANK], Ss[DG * RANK];
    __shared__ float A[DG * 33], P[DG * 33], Q[DG * 33];
    __shared__ float trR_sh;

    if (tid < DG * RANK) {
        Us[tid] = U[g * DG * RANK + tid];
        Vs[tid] = V[g * DG * RANK + tid];
        Ss[tid] = S[g * DG * RANK + tid];
    }
    __syncthreads();

    // trR = sum(S*S) over the group (one warp)
    if (tid < 32) {
        float s = 0.f;
        #pragma unroll
        for (int r = 0; r < RANK; ++r) {
            float v = Ss[tid * RANK + r];
            s = fmaf(v, v, s);
        }
        #pragma unroll
        for (int off = 16; off; off >>= 1)
            s += __shfl_xor_sync(0xffffffffu, s, off);
        if (tid == 0) trR_sh = s;
    }
    __syncthreads();

    // A[i][j] = sum_r (U[i,r]V[j,r] - V[i,r]U[j,r] - S[i,r]S[j,r]) + (i==j)*trR/dg
    {
        float a = 0.f;
        #pragma unroll
        for (int r = 0; r < RANK; ++r) {
            a = fmaf(Us[i * RANK + r],  Vs[j * RANK + r], a);
            a = fmaf(-Vs[i * RANK + r], Us[j * RANK + r], a);
            a = fmaf(-Ss[i * RANK + r], Ss[j * RANK + r], a);
        }
        if (i == j) a += trR_sh / (float)DG;
        A[i * 33 + j] = a;
    }
    __syncthreads();

    // P = I + dt A + 0.5 dt^2 A^2
    {
        float a2 = 0.f;
        #pragma unroll
        for (int k = 0; k < DG; ++k)
            a2 = fmaf(A[i * 33 + k], A[k * 33 + j], a2);
        float p = DT_C * A[i * 33 + j] + 0.5f * DT_C * DT_C * a2;
        if (i == j) p += 1.0f;
        P[i * 33 + j] = p;
    }
    __syncthreads();

    // Q = P*P
    {
        float q = 0.f;
        #pragma unroll
        for (int k = 0; k < DG; ++k)
            q = fmaf(P[i * 33 + k], P[k * 33 + j], q);
        Q[i * 33 + j] = q;
    }
    __syncthreads();

    // M = Q*Q  ->  global
    {
        float m = 0.f;
        #pragma unroll
        for (int k = 0; k < DG; ++k)
            m = fmaf(Q[i * 33 + k], Q[k * 33 + j], m);
        d_M[g * DG * DG + i * DG + j] = m;
    }
}

// ---------------------------------------------------------------------------
// One Chebyshev recurrence step:
//   tp := 2*Lhat(tc) - tp = -(left(tc) + right(tc)) - tp ;  y += ck * tp
// Column of 512 along W held lane-strided: element index w = lane + 32*i.
// Dirichlet zero boundaries at w=0 and w=511 via carry registers.
// ---------------------------------------------------------------------------
__device__ __forceinline__ void cheb_step(float (&tp)[WPL], const float (&tc)[WPL],
                                          float (&y)[WPL], float ck, int lane) {
    float carry = 0.f;
    #pragma unroll
    for (int i = 0; i < WPL; ++i) {
        float rl   = __shfl_sync(0xffffffffu, tc[i], (lane + 31) & 31);
        float left = (lane == 0) ? carry : rl;
        carry      = rl;                 // lane0's carry := lane31's tc[i]
        tp[i]      = -left - tp[i];
    }
    carry = 0.f;
    #pragma unroll
    for (int i = WPL - 1; i >= 0; --i) {
        float rr    = __shfl_sync(0xffffffffu, tc[i], (lane + 1) & 31);
        float right = (lane == 31) ? carry : rr;
        carry       = rr;                // lane31's carry := lane0's tc[i]
        tp[i]      -= right;
        y[i]        = fmaf(ck, tp[i], y[i]);
    }
}

// ---------------------------------------------------------------------------
// Fused kernel: norm -> Chebyshev -> matvec(M_g).  Block = (b, g), 1024 thr.
// ---------------------------------------------------------------------------
__global__ __launch_bounds__(1024, 1)
void continuous_block_kernel(const float* __restrict__ x,
                             const float* __restrict__ cheb,
                             float* __restrict__ out) {
    extern __shared__ float sm[];
    float* xn  = sm;                  // [32][513] transposed slab (channel-major)
    float* Msm = sm + DG * 513;       // [32][33]

    const int g  = blockIdx.x & (GROUPS - 1);
    const int b  = blockIdx.x >> 3;   // GROUPS == 8
    const int tid  = threadIdx.x;
    const int warp = tid >> 5;
    const int lane = tid & 31;

    // Stage M into padded smem (conflict-free later reads)
    Msm[warp * 33 + lane] = d_M[g * DG * DG + warp * DG + lane];

    // ---------------- Phase A: load + groupwise norm ----------------
    // warp j handles tokens w = j + 32*t ; lane = channel within group.
    // Fused (sum, sumsq) reduction: var = E[v^2] - mu^2.
    const size_t base = ((size_t)b * W_DIM) * D_DIM + (size_t)g * DG;
    #pragma unroll
    for (int t = 0; t < WPL; ++t) {
        const int w = warp + 32 * t;
        float v = x[base + (size_t)w * D_DIM + lane];
        float s  = v;
        float s2 = v * v;
        #pragma unroll
        for (int off = 16; off; off >>= 1) {
            s  += __shfl_xor_sync(0xffffffffu, s,  off);
            s2 += __shfl_xor_sync(0xffffffffu, s2, off);
        }
        const float mu  = s * (1.0f / DG);
        const float var = fmaf(s2, 1.0f / DG, -mu * mu);
        const float inv = rsqrtf(var + 1e-6f);
        xn[lane * 513 + w] = (v - mu) * inv;  // bank (lane + w) % 32 -> conflict-free
    }
    __syncthreads();

    // ---------------- Phase B: Chebyshev along W (warp = channel) ----------
    float cc[KCOEF];
    #pragma unroll
    for (int k = 0; k < KCOEF; ++k) cc[k] = __ldg(&cheb[g * KCOEF + k]);

    float t0[WPL], t1[WPL], y[WPL];
    const int c = warp;
    #pragma unroll
    for (int i = 0; i < WPL; ++i)
        t0[i] = xn[c * 513 + lane + 32 * i];

    // t1 = Lhat(t0) = -0.5*(left + right)
    {
        float carry = 0.f;
        #pragma unroll
        for (int i = 0; i < WPL; ++i) {
            float rl = __shfl_sync(0xffffffffu, t0[i], (lane + 31) & 31);
            t1[i]    = (lane == 0) ? carry : rl;
            carry    = rl;
        }
        carry = 0.f;
        #pragma unroll
        for (int i = WPL - 1; i >= 0; --i) {
            float rr    = __shfl_sync(0xffffffffu, t0[i], (lane + 1) & 31);
            float right = (lane == 31) ? carry : rr;
            carry       = rr;
            t1[i]       = -0.5f * (t1[i] + right);
        }
    }
    #pragma unroll
    for (int i = 0; i < WPL; ++i)
        y[i] = fmaf(cc[1], t1[i], cc[0] * t0[i]);

    cheb_step(t0, t1, y, cc[2], lane);   // t0 := T2
    cheb_step(t1, t0, y, cc[3], lane);   // t1 := T3
    cheb_step(t0, t1, y, cc[4], lane);   // t0 := T4
    cheb_step(t1, t0, y, cc[5], lane);   // t1 := T5
    cheb_step(t0, t1, y, cc[6], lane);   // t0 := T6
    cheb_step(t1, t0, y, cc[7], lane);   // t1 := T7
    cheb_step(t0, t1, y, cc[8], lane);   // t0 := T8

    // write filtered column back in place (only this warp touches row c)
    #pragma unroll
    for (int i = 0; i < WPL; ++i)
        xn[c * 513 + lane + 32 * i] = y[i];
    __syncthreads();

    // ---------------- Phase C: z = M_g * y per token (warp = token set) ----
    float Mreg[DG];
    #pragma unroll
    for (int k = 0; k < DG; ++k)
        Mreg[k] = Msm[lane * 33 + k];   // lane = output channel; conflict-free

    #pragma unroll
    for (int t = 0; t < WPL; ++t) {
        const int w = warp + 32 * t;
        float a0 = 0.f, a1 = 0.f, a2 = 0.f, a3 = 0.f;
        #pragma unroll
        for (int k = 0; k < DG; k += 4) {
            a0 = fmaf(Mreg[k + 0], xn[(k + 0) * 513 + w], a0);  // broadcast reads
            a1 = fmaf(Mreg[k + 1], xn[(k + 1) * 513 + w], a1);
            a2 = fmaf(Mreg[k + 2], xn[(k + 2) * 513 + w], a2);
            a3 = fmaf(Mreg[k + 3], xn[(k + 3) * 513 + w], a3);
        }
        out[base + (size_t)w * D_DIM + lane] = (a0 + a1) + (a2 + a3);
    }
}

// ---------------------------------------------------------------------------
extern "C" void kernel_launch(void* const* d_in, const int* in_sizes, int n_in,
                              void* d_out, int out_size) {
    const float* x    = (const float*)d_in[0];
    const float* cheb = (const float*)d_in[1];
    const float* U    = (const float*)d_in[2];
    const float* V    = (const float*)d_in[3];
    const float* S    = (const float*)d_in[4];
    float* out = (float*)d_out;

    const int B = in_sizes[0] / (W_DIM * D_DIM);

    const size_t smem = (DG * 513 + DG * 33) * sizeof(float);  // 69888 B
    cudaFuncSetAttribute(continuous_block_kernel,
                         cudaFuncAttributeMaxDynamicSharedMemorySize, (int)smem);

    precompute_M_kernel<<<GROUPS, 1024>>>(U, V, S);
    continuous_block_kernel<<<B * GROUPS, 1024, smem>>>(x, cheb, out);
}

// round 3
// speedup vs baseline: 1.7367x; 1.7367x over previous
#include <cuda_runtime.h>
#include <cuda_bf16.h>
#include <math.h>

// Problem constants (fixed by the reference)
#define GROUPS 8
#define DG     32        // D / GROUPS
#define W_DIM  512
#define D_DIM  256
#define KCOEF  9         // CHEB_DEG + 1
#define RANK   16
#define DT_C   0.1f
#define XS     516       // xn row stride in floats (516*4 % 16 == 0; 516 % 32 == 4)
#define MS     36        // M row stride in floats (36*4 % 16 == 0)
#define FULL   0xffffffffu

// Precomputed per-group integration matrix M_g = (I + dt A + 0.5 dt^2 A^2)^4
__device__ float d_M[GROUPS * DG * DG];

// ---------------------------------------------------------------------------
// Precompute kernel: one block per group, 1024 threads (i = tid>>5, j = tid&31)
// ---------------------------------------------------------------------------
__global__ void precompute_M_kernel(const float* __restrict__ U,
                                    const float* __restrict__ V,
                                    const float* __restrict__ S) {
    const int g   = blockIdx.x;
    const int tid = threadIdx.x;
    const int i   = tid >> 5;
    const int j   = tid & 31;

    __shared__ float Us[DG * RANK], Vs[DG * RANK], Ss[DG * RANK];
    __shared__ float A[DG * 33], P[DG * 33], Q[DG * 33];
    __shared__ float trR_sh;

    if (tid < DG * RANK) {
        Us[tid] = U[g * DG * RANK + tid];
        Vs[tid] = V[g * DG * RANK + tid];
        Ss[tid] = S[g * DG * RANK + tid];
    }
    __syncthreads();

    if (tid < 32) {
        float s = 0.f;
        #pragma unroll
        for (int r = 0; r < RANK; ++r) {
            float v = Ss[tid * RANK + r];
            s = fmaf(v, v, s);
        }
        #pragma unroll
        for (int off = 16; off; off >>= 1)
            s += __shfl_xor_sync(FULL, s, off);
        if (tid == 0) trR_sh = s;
    }
    __syncthreads();

    {
        float a = 0.f;
        #pragma unroll
        for (int r = 0; r < RANK; ++r) {
            a = fmaf(Us[i * RANK + r],  Vs[j * RANK + r], a);
            a = fmaf(-Vs[i * RANK + r], Us[j * RANK + r], a);
            a = fmaf(-Ss[i * RANK + r], Ss[j * RANK + r], a);
        }
        if (i == j) a += trR_sh / (float)DG;
        A[i * 33 + j] = a;
    }
    __syncthreads();

    {
        float a2 = 0.f;
        #pragma unroll
        for (int k = 0; k < DG; ++k)
            a2 = fmaf(A[i * 33 + k], A[k * 33 + j], a2);
        float p = DT_C * A[i * 33 + j] + 0.5f * DT_C * DT_C * a2;
        if (i == j) p += 1.0f;
        P[i * 33 + j] = p;
    }
    __syncthreads();

    {
        float q = 0.f;
        #pragma unroll
        for (int k = 0; k < DG; ++k)
            q = fmaf(P[i * 33 + k], P[k * 33 + j], q);
        Q[i * 33 + j] = q;
    }
    __syncthreads();

    {
        float m = 0.f;
        #pragma unroll
        for (int k = 0; k < DG; ++k)
            m = fmaf(Q[i * 33 + k], Q[k * 33 + j], m);
        d_M[g * DG * DG + i * DG + j] = m;
    }
}

// ---------------------------------------------------------------------------
// float4 helpers (componentwise, stays in registers)
// ---------------------------------------------------------------------------
__device__ __forceinline__ float4 f4_fma(float a, const float4 v, const float4 acc) {
    return make_float4(fmaf(a, v.x, acc.x), fmaf(a, v.y, acc.y),
                       fmaf(a, v.z, acc.z), fmaf(a, v.w, acc.w));
}
__device__ __forceinline__ float4 f4_negsub(const float4 s, const float4 t) {
    return make_float4(-s.x - t.x, -s.y - t.y, -s.z - t.z, -s.w - t.w);
}

// Neighbor sums for the path-Laplacian stencil on layout w = 128*i + 4*lane + j.
// s[i].c = x[w-1] + x[w+1] with Dirichlet zeros at w=0 and w=511.
// Only 8 shuffles per application (block boundaries); interior neighbors are
// register reads within the float4.
__device__ __forceinline__ void nbr_sum(const float4 (&t)[4], float4 (&s)[4], int lane) {
    float rl[4], rr[4];
    #pragma unroll
    for (int i = 0; i < 4; ++i) {
        rl[i] = __shfl_sync(FULL, t[i].w, (lane + 31) & 31);  // from lane-1
        rr[i] = __shfl_sync(FULL, t[i].x, (lane + 1) & 31);   // from lane+1
    }
    #pragma unroll
    for (int i = 0; i < 4; ++i) {
        // lane 0's rl[i] came from lane 31 (wrong block) -> use rl[i-1], which at
        // lane 0 holds lane31's t[i-1].w = element w = 128*i - 1. i==0 -> boundary 0.
        float lft = (lane != 0)  ? rl[i] : (i > 0 ? rl[i - 1] : 0.f);
        float rgt = (lane != 31) ? rr[i] : (i < 3 ? rr[i + 1] : 0.f);
        s[i].x = lft     + t[i].y;
        s[i].y = t[i].x  + t[i].z;
        s[i].z = t[i].y  + t[i].w;
        s[i].w = t[i].z  + rgt;
    }
}

// One Chebyshev recurrence step: tp := -(left+right)(tc) - tp ;  y += ck*tp
__device__ __forceinline__ void cheb_step4(float4 (&tp)[4], const float4 (&tc)[4],
                                           float4 (&y)[4], float ck, int lane) {
    float4 s[4];
    nbr_sum(tc, s, lane);
    #pragma unroll
    for (int i = 0; i < 4; ++i) {
        tp[i] = f4_negsub(s[i], tp[i]);
        y[i]  = f4_fma(ck, tp[i], y[i]);
    }
}

// ---------------------------------------------------------------------------
// Fused kernel: norm -> Chebyshev -> matvec(M_g).  Block = (b, g), 1024 thr.
// ---------------------------------------------------------------------------
__global__ __launch_bounds__(1024, 1)
void continuous_block_kernel(const float* __restrict__ x,
                             const float* __restrict__ cheb,
                             float* __restrict__ out) {
    extern __shared__ float sm[];
    float* xn  = sm;                    // [32][XS] channel-major slab
    float* Msm = sm + DG * XS;          // [32][MS]
    float* csm = Msm + DG * MS;         // [KCOEF]

    const int g    = blockIdx.x & (GROUPS - 1);
    const int b    = blockIdx.x >> 3;
    const int tid  = threadIdx.x;
    const int warp = tid >> 5;
    const int lane = tid & 31;

    Msm[warp * MS + lane] = d_M[g * DG * DG + warp * DG + lane];
    if (tid < KCOEF) csm[tid] = cheb[g * KCOEF + tid];

    const size_t base = ((size_t)b * W_DIM) * D_DIM + (size_t)g * DG;
    const int wb = warp * 16;           // this warp's 16 consecutive tokens

    // ---------------- Phase A: load + groupwise norm (vectorized stores) ----
    #pragma unroll
    for (int tb = 0; tb < 4; ++tb) {
        float4 acc;
        #pragma unroll
        for (int j = 0; j < 4; ++j) {
            const int w = wb + tb * 4 + j;
            float v  = x[base + (size_t)w * D_DIM + lane];
            float s  = v;
            float s2 = v * v;
            #pragma unroll
            for (int off = 16; off; off >>= 1) {
                s  += __shfl_xor_sync(FULL, s,  off);
                s2 += __shfl_xor_sync(FULL, s2, off);
            }
            const float mu  = s * (1.0f / DG);
            const float var = fmaf(s2, 1.0f / DG, -mu * mu);
            const float nv  = (v - mu) * rsqrtf(var + 1e-6f);
            if      (j == 0) acc.x = nv;
            else if (j == 1) acc.y = nv;
            else if (j == 2) acc.z = nv;
            else             acc.w = nv;
        }
        // stride 516: bank group (4*lane + w0) % 32 -> conflict-free STS.128
        *reinterpret_cast<float4*>(&xn[lane * XS + wb + tb * 4]) = acc;
    }
    __syncthreads();

    // ---------------- Phase B: Chebyshev along W (warp = channel) ----------
    const int c = warp;
    float4 t0[4], t1[4], y[4];
    #pragma unroll
    for (int i = 0; i < 4; ++i)
        t0[i] = *reinterpret_cast<const float4*>(&xn[c * XS + i * 128 + lane * 4]);

    // t1 = Lhat(t0) = -0.5*(left+right)
    {
        float4 s[4];
        nbr_sum(t0, s, lane);
        const float c0 = csm[0], c1 = csm[1];
        #pragma unroll
        for (int i = 0; i < 4; ++i) {
            t1[i] = make_float4(-0.5f * s[i].x, -0.5f * s[i].y,
                                -0.5f * s[i].z, -0.5f * s[i].w);
            y[i]  = make_float4(fmaf(c1, t1[i].x, c0 * t0[i].x),
                                fmaf(c1, t1[i].y, c0 * t0[i].y),
                                fmaf(c1, t1[i].z, c0 * t0[i].z),
                                fmaf(c1, t1[i].w, c0 * t0[i].w));
        }
    }
    cheb_step4(t0, t1, y, csm[2], lane);   // t0 := T2
    cheb_step4(t1, t0, y, csm[3], lane);   // t1 := T3
    cheb_step4(t0, t1, y, csm[4], lane);   // t0 := T4
    cheb_step4(t1, t0, y, csm[5], lane);   // t1 := T5
    cheb_step4(t0, t1, y, csm[6], lane);   // t0 := T6
    cheb_step4(t1, t0, y, csm[7], lane);   // t1 := T7
    cheb_step4(t0, t1, y, csm[8], lane);   // t0 := T8

    // write filtered column back in place (only this warp touches row c)
    #pragma unroll
    for (int i = 0; i < 4; ++i)
        *reinterpret_cast<float4*>(&xn[c * XS + i * 128 + lane * 4]) = y[i];
    __syncthreads();

    // ---------------- Phase C: z = M_g * y ; lane = out channel, 4 tokens/iter
    float Mreg[DG];
    #pragma unroll
    for (int k8 = 0; k8 < 8; ++k8) {
        float4 m = *reinterpret_cast<const float4*>(&Msm[lane * MS + k8 * 4]);
        Mreg[4 * k8 + 0] = m.x;  Mreg[4 * k8 + 1] = m.y;
        Mreg[4 * k8 + 2] = m.z;  Mreg[4 * k8 + 3] = m.w;
    }

    #pragma unroll
    for (int tb = 0; tb < 4; ++tb) {
        const int w0 = wb + tb * 4;
        float zx = 0.f, zy = 0.f, zz = 0.f, zw = 0.f;
        #pragma unroll
        for (int k = 0; k < DG; ++k) {
            // uniform address -> broadcast LDS.128 serving 4 tokens at once
            float4 yv = *reinterpret_cast<const float4*>(&xn[k * XS + w0]);
            zx = fmaf(Mreg[k], yv.x, zx);
            zy = fmaf(Mreg[k], yv.y, zy);
            zz = fmaf(Mreg[k], yv.z, zz);
            zw = fmaf(Mreg[k], yv.w, zw);
        }
        float* o = &out[base + (size_t)w0 * D_DIM + lane];
        o[0 * D_DIM] = zx;
        o[1 * D_DIM] = zy;
        o[2 * D_DIM] = zz;
        o[3 * D_DIM] = zw;
    }
}

// ---------------------------------------------------------------------------
extern "C" void kernel_launch(void* const* d_in, const int* in_sizes, int n_in,
                              void* d_out, int out_size) {
    const float* x    = (const float*)d_in[0];
    const float* cheb = (const float*)d_in[1];
    const float* U    = (const float*)d_in[2];
    const float* V    = (const float*)d_in[3];
    const float* S    = (const float*)d_in[4];
    float* out = (float*)d_out;

    const int B = in_sizes[0] / (W_DIM * D_DIM);

    const size_t smem = (DG * XS + DG * MS + 16) * sizeof(float);  // ~70.7 KB
    cudaFuncSetAttribute(continuous_block_kernel,
                         cudaFuncAttributeMaxDynamicSharedMemorySize, (int)smem);

    precompute_M_kernel<<<GROUPS, 1024>>>(U, V, S);
    continuous_block_kernel<<<B * GROUPS, 1024, smem>>>(x, cheb, out);
}

// round 4
// speedup vs baseline: 2.0925x; 1.2049x over previous
#include <cuda_runtime.h>
#include <cuda_bf16.h>
#include <math.h>

// Problem constants (fixed by the reference)
#define GROUPS 8
#define DG     32        // D / GROUPS
#define W_DIM  512
#define D_DIM  256
#define KCOEF  9         // CHEB_DEG + 1
#define RANK   16
#define DT_C   0.1f
#define XS     516       // xn row stride in floats (c*XS mod 32 = 4c mod 32)
#define MS     33        // M row stride in floats (scalar access, conflict-free)
#define FULL   0xffffffffu

// Precomputed per-group integration matrix M_g = (I + dt A + 0.5 dt^2 A^2)^4
__device__ float d_M[GROUPS * DG * DG];

// ---------------------------------------------------------------------------
// Precompute kernel: one block per group, 1024 threads (i = tid>>5, j = tid&31)
// ---------------------------------------------------------------------------
__global__ void precompute_M_kernel(const float* __restrict__ U,
                                    const float* __restrict__ V,
                                    const float* __restrict__ S) {
    const int g   = blockIdx.x;
    const int tid = threadIdx.x;
    const int i   = tid >> 5;
    const int j   = tid & 31;

    __shared__ float Us[DG * RANK], Vs[DG * RANK], Ss[DG * RANK];
    __shared__ float A[DG * 33], P[DG * 33], Q[DG * 33];
    __shared__ float trR_sh;

    if (tid < DG * RANK) {
        Us[tid] = U[g * DG * RANK + tid];
        Vs[tid] = V[g * DG * RANK + tid];
        Ss[tid] = S[g * DG * RANK + tid];
    }
    __syncthreads();

    if (tid < 32) {
        float s = 0.f;
        #pragma unroll
        for (int r = 0; r < RANK; ++r) {
            float v = Ss[tid * RANK + r];
            s = fmaf(v, v, s);
        }
        #pragma unroll
        for (int off = 16; off; off >>= 1)
            s += __shfl_xor_sync(FULL, s, off);
        if (tid == 0) trR_sh = s;
    }
    __syncthreads();

    {
        float a = 0.f;
        #pragma unroll
        for (int r = 0; r < RANK; ++r) {
            a = fmaf(Us[i * RANK + r],  Vs[j * RANK + r], a);
            a = fmaf(-Vs[i * RANK + r], Us[j * RANK + r], a);
            a = fmaf(-Ss[i * RANK + r], Ss[j * RANK + r], a);
        }
        if (i == j) a += trR_sh / (float)DG;
        A[i * 33 + j] = a;
    }
    __syncthreads();

    {
        float a2 = 0.f;
        #pragma unroll
        for (int k = 0; k < DG; ++k)
            a2 = fmaf(A[i * 33 + k], A[k * 33 + j], a2);
        float p = DT_C * A[i * 33 + j] + 0.5f * DT_C * DT_C * a2;
        if (i == j) p += 1.0f;
        P[i * 33 + j] = p;
    }
    __syncthreads();

    {
        float q = 0.f;
        #pragma unroll
        for (int k = 0; k < DG; ++k)
            q = fmaf(P[i * 33 + k], P[k * 33 + j], q);
        Q[i * 33 + j] = q;
    }
    __syncthreads();

    {
        float m = 0.f;
        #pragma unroll
        for (int k = 0; k < DG; ++k)
            m = fmaf(Q[i * 33 + k], Q[k * 33 + j], m);
        d_M[g * DG * DG + i * DG + j] = m;
    }
}

// ---------------------------------------------------------------------------
// float4 helpers
// ---------------------------------------------------------------------------
__device__ __forceinline__ float4 f4_fma(float a, const float4 v, const float4 acc) {
    return make_float4(fmaf(a, v.x, acc.x), fmaf(a, v.y, acc.y),
                       fmaf(a, v.z, acc.z), fmaf(a, v.w, acc.w));
}
__device__ __forceinline__ float4 f4_negsub(const float4 s, const float4 t) {
    return make_float4(-s.x - t.x, -s.y - t.y, -s.z - t.z, -s.w - t.w);
}

// Neighbor sums for the path-Laplacian stencil, layout w = 128*i + 4*lane + j.
// s[i].c = x[w-1] + x[w+1]; Dirichlet zeros at w=0 and w=511.
__device__ __forceinline__ void nbr_sum(const float4 (&t)[4], float4 (&s)[4], int lane) {
    float rl[4], rr[4];
    #pragma unroll
    for (int i = 0; i < 4; ++i) {
        rl[i] = __shfl_sync(FULL, t[i].w, (lane + 31) & 31);  // from lane-1
        rr[i] = __shfl_sync(FULL, t[i].x, (lane + 1) & 31);   // from lane+1
    }
    #pragma unroll
    for (int i = 0; i < 4; ++i) {
        float lft = (lane != 0)  ? rl[i] : (i > 0 ? rl[i - 1] : 0.f);
        float rgt = (lane != 31) ? rr[i] : (i < 3 ? rr[i + 1] : 0.f);
        s[i].x = lft     + t[i].y;
        s[i].y = t[i].x  + t[i].z;
        s[i].z = t[i].y  + t[i].w;
        s[i].w = t[i].z  + rgt;
    }
}

__device__ __forceinline__ void cheb_step4(float4 (&tp)[4], const float4 (&tc)[4],
                                           float4 (&y)[4], float ck, int lane) {
    float4 s[4];
    nbr_sum(tc, s, lane);
    #pragma unroll
    for (int i = 0; i < 4; ++i) {
        tp[i] = f4_negsub(s[i], tp[i]);
        y[i]  = f4_fma(ck, tp[i], y[i]);
    }
}

// ---------------------------------------------------------------------------
// Fused kernel: norm -> Chebyshev -> matvec(M_g).  Block = (b, g), 1024 thr.
// Slab addressing: logical token-block B (w>>2) of channel c lives at float
// offset  c*XS + 4*(B ^ (c>>2)) + (w&3).   XOR swizzle makes Phase A's
// transposed scalar stores conflict-free while Phase B float4 accesses see
// only a lane permutation (still conflict-free) and Phase C broadcasts are
// unaffected.
// ---------------------------------------------------------------------------
__global__ __launch_bounds__(1024, 1)
void continuous_block_kernel(const float* __restrict__ x,
                             const float* __restrict__ cheb,
                             float* __restrict__ out) {
    extern __shared__ float sm[];
    float* xn  = sm;                    // [32][XS] channel-major swizzled slab
    float* Msm = sm + DG * XS;          // [32][MS]
    float* csm = Msm + DG * MS;         // [KCOEF]

    const int g    = blockIdx.x & (GROUPS - 1);
    const int b    = blockIdx.x >> 3;
    const int tid  = threadIdx.x;
    const int warp = tid >> 5;
    const int lane = tid & 31;

    Msm[warp * MS + lane] = d_M[g * DG * DG + warp * DG + lane];  // conflict-free
    if (tid < KCOEF) csm[tid] = cheb[g * KCOEF + tid];

    const size_t base = ((size_t)b * W_DIM) * D_DIM + (size_t)g * DG;
    const int wb = warp * 16;           // this warp's 16 consecutive tokens

    // ---------------- Phase A: load + groupwise norm ------------------------
    // lane = 8*tg + c4 : tg = token-in-quad, c4 = channel quad.
    // One LDG.128 per tb; (sum,sumsq) butterfly over 8 lanes (6 shuffles).
    {
        const int tg = lane >> 3;
        const int c4 = lane & 7;
        float4 v[4];
        #pragma unroll
        for (int tb = 0; tb < 4; ++tb) {
            const int w = wb + tb * 4 + tg;
            v[tb] = *reinterpret_cast<const float4*>(
                        &x[base + (size_t)w * D_DIM + c4 * 4]);
        }
        #pragma unroll
        for (int tb = 0; tb < 4; ++tb) {
            float s  = v[tb].x + v[tb].y + v[tb].z + v[tb].w;
            float s2 = fmaf(v[tb].x, v[tb].x, fmaf(v[tb].y, v[tb].y,
                       fmaf(v[tb].z, v[tb].z, v[tb].w * v[tb].w)));
            #pragma unroll
            for (int off = 4; off; off >>= 1) {       // within 8-lane group
                s  += __shfl_xor_sync(FULL, s,  off);
                s2 += __shfl_xor_sync(FULL, s2, off);
            }
            const float mu  = s * (1.0f / DG);
            const float var = fmaf(s2, 1.0f / DG, -mu * mu);
            const float inv = rsqrtf(var + 1e-6f);
            const float nx = (v[tb].x - mu) * inv;
            const float ny = (v[tb].y - mu) * inv;
            const float nz = (v[tb].z - mu) * inv;
            const float nw = (v[tb].w - mu) * inv;
            const int T = warp * 4 + tb;              // token block (w>>2)
            // channel c = 4*c4 + j ; swizzled scalar stores, all banks distinct
            const int sw = 4 * (T ^ c4);              // c>>2 == c4 for all j
            xn[(4 * c4 + 0) * XS + sw + tg] = nx;
            xn[(4 * c4 + 1) * XS + sw + tg] = ny;
            xn[(4 * c4 + 2) * XS + sw + tg] = nz;
            xn[(4 * c4 + 3) * XS + sw + tg] = nw;
        }
    }
    __syncthreads();

    // ---------------- Phase B: Chebyshev along W (warp = channel) ----------
    const int c  = warp;
    const int sc = c >> 2;              // row swizzle key
    float4 t0[4], t1[4], y[4];
    #pragma unroll
    for (int i = 0; i < 4; ++i)
        t0[i] = *reinterpret_cast<const float4*>(
                    &xn[c * XS + 4 * ((i * 32 + lane) ^ sc)]);

    {
        float4 s[4];
        nbr_sum(t0, s, lane);
        const float c0 = csm[0], c1 = csm[1];
        #pragma unroll
        for (int i = 0; i < 4; ++i) {
            t1[i] = make_float4(-0.5f * s[i].x, -0.5f * s[i].y,
                                -0.5f * s[i].z, -0.5f * s[i].w);
            y[i]  = make_float4(fmaf(c1, t1[i].x, c0 * t0[i].x),
                                fmaf(c1, t1[i].y, c0 * t0[i].y),
                                fmaf(c1, t1[i].z, c0 * t0[i].z),
                                fmaf(c1, t1[i].w, c0 * t0[i].w));
        }
    }
    cheb_step4(t0, t1, y, csm[2], lane);   // T2
    cheb_step4(t1, t0, y, csm[3], lane);   // T3
    cheb_step4(t0, t1, y, csm[4], lane);   // T4
    cheb_step4(t1, t0, y, csm[5], lane);   // T5
    cheb_step4(t0, t1, y, csm[6], lane);   // T6
    cheb_step4(t1, t0, y, csm[7], lane);   // T7
    cheb_step4(t0, t1, y, csm[8], lane);   // T8

    #pragma unroll
    for (int i = 0; i < 4; ++i)
        *reinterpret_cast<float4*>(
            &xn[c * XS + 4 * ((i * 32 + lane) ^ sc)]) = y[i];
    __syncthreads();

    // ---------------- Phase C: z = M_g * y ; lane = out channel ------------
    float Mreg[DG];
    #pragma unroll
    for (int k = 0; k < DG; ++k)
        Mreg[k] = Msm[lane * MS + k];   // conflict-free scalar

    #pragma unroll
    for (int tb = 0; tb < 4; ++tb) {
        const int w0 = wb + tb * 4;
        const int T  = w0 >> 2;
        float zx = 0.f, zy = 0.f, zz = 0.f, zw = 0.f;
        #pragma unroll
        for (int k = 0; k < DG; ++k) {
            // uniform address -> broadcast LDS.128 serving 4 tokens
            float4 yv = *reinterpret_cast<const float4*>(
                            &xn[k * XS + 4 * (T ^ (k >> 2))]);
            zx = fmaf(Mreg[k], yv.x, zx);
            zy = fmaf(Mreg[k], yv.y, zy);
            zz = fmaf(Mreg[k], yv.z, zz);
            zw = fmaf(Mreg[k], yv.w, zw);
        }
        float* o = &out[base + (size_t)w0 * D_DIM + lane];
        o[0 * D_DIM] = zx;
        o[1 * D_DIM] = zy;
        o[2 * D_DIM] = zz;
        o[3 * D_DIM] = zw;
    }
}

// ---------------------------------------------------------------------------
extern "C" void kernel_launch(void* const* d_in, const int* in_sizes, int n_in,
                              void* d_out, int out_size) {
    const float* x    = (const float*)d_in[0];
    const float* cheb = (const float*)d_in[1];
    const float* U    = (const float*)d_in[2];
    const float* V    = (const float*)d_in[3];
    const float* S    = (const float*)d_in[4];
    float* out = (float*)d_out;

    const int B = in_sizes[0] / (W_DIM * D_DIM);

    const size_t smem = (DG * XS + DG * MS + 16) * sizeof(float);  // ~70.4 KB
    cudaFuncSetAttribute(continuous_block_kernel,
                         cudaFuncAttributeMaxDynamicSharedMemorySize, (int)smem);

    precompute_M_kernel<<<GROUPS, 1024>>>(U, V, S);
    continuous_block_kernel<<<B * GROUPS, 1024, smem>>>(x, cheb, out);
}

// round 7
// speedup vs baseline: 2.3574x; 1.1266x over previous
#include <cuda_runtime.h>
#include <cuda_bf16.h>
#include <math.h>

// Problem constants (fixed by the reference)
#define GROUPS 8
#define DG     32        // D / GROUPS
#define W_DIM  512
#define D_DIM  256
#define KCOEF  9         // CHEB_DEG + 1
#define RANK   16
#define DT_C   0.1f
#define XS     516       // xn row stride in floats (XS mod 32 == 4)
#define MS     33        // M row stride (scalar access, conflict-free)
#define FULL   0xffffffffu

// Slab layout:  addr(c, w) = c*XS + 4*((l + 32*j4) ^ (c>>2)) + (w&3)
//   where l = w>>4 (owning lane in Phase B), j4 = (w>>2)&3.
// Conflict-free for: Phase A transposed scalar stores, Phase B per-lane
// contiguous float4 loads/stores, Phase C uniform broadcast reads.

// Precomputed per-group integration matrix M_g = (I + dt A + 0.5 dt^2 A^2)^4
__device__ float d_M[GROUPS * DG * DG];

// ---------------------------------------------------------------------------
// Precompute kernel: one block per group, 1024 threads (i = tid>>5, j = tid&31)
// ---------------------------------------------------------------------------
__global__ void precompute_M_kernel(const float* __restrict__ U,
                                    const float* __restrict__ V,
                                    const float* __restrict__ S) {
    const int g   = blockIdx.x;
    const int tid = threadIdx.x;
    const int i   = tid >> 5;
    const int j   = tid & 31;

    __shared__ float Us[DG * RANK], Vs[DG * RANK], Ss[DG * RANK];
    __shared__ float A[DG * 33], P[DG * 33], Q[DG * 33];
    __shared__ float trR_sh;

    if (tid < DG * RANK) {
        Us[tid] = U[g * DG * RANK + tid];
        Vs[tid] = V[g * DG * RANK + tid];
        Ss[tid] = S[g * DG * RANK + tid];
    }
    __syncthreads();

    if (tid < 32) {
        float s = 0.f;
        #pragma unroll
        for (int r = 0; r < RANK; ++r) {
            float v = Ss[tid * RANK + r];
            s = fmaf(v, v, s);
        }
        #pragma unroll
        for (int off = 16; off; off >>= 1)
            s += __shfl_xor_sync(FULL, s, off);
        if (tid == 0) trR_sh = s;
    }
    __syncthreads();

    {
        float a = 0.f;
        #pragma unroll
        for (int r = 0; r < RANK; ++r) {
            a = fmaf(Us[i * RANK + r],  Vs[j * RANK + r], a);
            a = fmaf(-Vs[i * RANK + r], Us[j * RANK + r], a);
            a = fmaf(-Ss[i * RANK + r], Ss[j * RANK + r], a);
        }
        if (i == j) a += trR_sh / (float)DG;
        A[i * 33 + j] = a;
    }
    __syncthreads();

    {
        float a2 = 0.f;
        #pragma unroll
        for (int k = 0; k < DG; ++k)
            a2 = fmaf(A[i * 33 + k], A[k * 33 + j], a2);
        float p = DT_C * A[i * 33 + j] + 0.5f * DT_C * DT_C * a2;
        if (i == j) p += 1.0f;
        P[i * 33 + j] = p;
    }
    __syncthreads();

    {
        float q = 0.f;
        #pragma unroll
        for (int k = 0; k < DG; ++k)
            q = fmaf(P[i * 33 + k], P[k * 33 + j], q);
        Q[i * 33 + j] = q;
    }
    __syncthreads();

    {
        float m = 0.f;
        #pragma unroll
        for (int k = 0; k < DG; ++k)
            m = fmaf(Q[i * 33 + k], Q[k * 33 + j], m);
        d_M[g * DG * DG + i * DG + j] = m;
    }
}

// ---------------------------------------------------------------------------
// float4 helpers
// ---------------------------------------------------------------------------
__device__ __forceinline__ float4 f4_fma(float a, const float4 v, const float4 acc) {
    return make_float4(fmaf(a, v.x, acc.x), fmaf(a, v.y, acc.y),
                       fmaf(a, v.z, acc.z), fmaf(a, v.w, acc.w));
}
__device__ __forceinline__ float4 f4_negsub(const float4 s, const float4 t) {
    return make_float4(-s.x - t.x, -s.y - t.y, -s.z - t.z, -s.w - t.w);
}

// Neighbor sums for the path-Laplacian stencil. Each lane holds 16 CONTIGUOUS
// tokens w = 16*lane + j (t[4] float4s). Only 2 shuffles per application;
// Dirichlet zeros at w=0 and w=511.
__device__ __forceinline__ void nbr_sum16(const float4 (&t)[4], float4 (&s)[4], int lane) {
    float tl = __shfl_sync(FULL, t[3].w, (lane + 31) & 31);  // lane-1's last
    float tr = __shfl_sync(FULL, t[0].x, (lane + 1) & 31);   // lane+1's first
    if (lane == 0)  tl = 0.f;
    if (lane == 31) tr = 0.f;
    #pragma unroll
    for (int i = 0; i < 4; ++i) {
        s[i].x = (i > 0 ? t[i - 1].w : tl) + t[i].y;
        s[i].y = t[i].x + t[i].z;
        s[i].z = t[i].y + t[i].w;
        s[i].w = t[i].z + (i < 3 ? t[i + 1].x : tr);
    }
}

// One Chebyshev recurrence step: tp := -(left+right)(tc) - tp ;  y += ck*tp
__device__ __forceinline__ void cheb_step16(float4 (&tp)[4], const float4 (&tc)[4],
                                            float4 (&y)[4], float ck, int lane) {
    float4 s[4];
    nbr_sum16(tc, s, lane);
    #pragma unroll
    for (int i = 0; i < 4; ++i) {
        tp[i] = f4_negsub(s[i], tp[i]);
        y[i]  = f4_fma(ck, tp[i], y[i]);
    }
}

// ---------------------------------------------------------------------------
// Fused kernel: norm -> Chebyshev -> matvec(M_g).  Block = (b, g), 1024 thr.
// ---------------------------------------------------------------------------
__global__ __launch_bounds__(1024, 1)
void continuous_block_kernel(const float* __restrict__ x,
                             const float* __restrict__ cheb,
                             float* __restrict__ out) {
    extern __shared__ float sm[];
    float* xn  = sm;                    // [32][XS] channel-major swizzled slab
    float* Msm = sm + DG * XS;          // [32][MS]
    float* csm = Msm + DG * MS;         // [KCOEF]

    const int g    = blockIdx.x & (GROUPS - 1);
    const int b    = blockIdx.x >> 3;
    const int tid  = threadIdx.x;
    const int warp = tid >> 5;
    const int lane = tid & 31;

    Msm[warp * MS + lane] = d_M[g * DG * DG + warp * DG + lane];  // conflict-free
    if (tid < KCOEF) csm[tid] = cheb[g * KCOEF + tid];

    const size_t base = ((size_t)b * W_DIM) * D_DIM + (size_t)g * DG;
    const int wb = warp * 16;           // this warp's 16 consecutive tokens

    // ---------------- Phase A: load + groupwise norm ------------------------
    // lane = 8*tg + c4 : tg = token-in-quad (w&3), c4 = channel quad.
    // Token w = 16*warp + 4*tb + tg  ->  l = warp, j4 = tb in the slab layout.
    {
        const int tg = lane >> 3;
        const int c4 = lane & 7;
        float4 v[4];
        #pragma unroll
        for (int tb = 0; tb < 4; ++tb) {
            const int w = wb + tb * 4 + tg;
            v[tb] = *reinterpret_cast<const float4*>(
                        &x[base + (size_t)w * D_DIM + c4 * 4]);
        }
        #pragma unroll
        for (int tb = 0; tb < 4; ++tb) {
            float s  = v[tb].x + v[tb].y + v[tb].z + v[tb].w;
            float s2 = fmaf(v[tb].x, v[tb].x, fmaf(v[tb].y, v[tb].y,
                       fmaf(v[tb].z, v[tb].z, v[tb].w * v[tb].w)));
            #pragma unroll
            for (int off = 4; off; off >>= 1) {       // within 8-lane group
                s  += __shfl_xor_sync(FULL, s,  off);
                s2 += __shfl_xor_sync(FULL, s2, off);
            }
            const float mu  = s * (1.0f / DG);
            const float var = fmaf(s2, 1.0f / DG, -mu * mu);
            const float inv = rsqrtf(var + 1e-6f);
            const float nx = (v[tb].x - mu) * inv;
            const float ny = (v[tb].y - mu) * inv;
            const float nz = (v[tb].z - mu) * inv;
            const float nw = (v[tb].w - mu) * inv;
            // slot = (l + 32*j4) ^ (c>>2), with l = warp, j4 = tb, c>>2 = c4
            const int off4 = 4 * ((warp + 32 * tb) ^ c4) + tg;
            xn[(4 * c4 + 0) * XS + off4] = nx;
            xn[(4 * c4 + 1) * XS + off4] = ny;
            xn[(4 * c4 + 2) * XS + off4] = nz;
            xn[(4 * c4 + 3) * XS + off4] = nw;
        }
    }
    __syncthreads();

    // ---------------- Phase B: Chebyshev along W (warp = channel) ----------
    // Lane holds 16 contiguous tokens w = 16*lane .. 16*lane+15.
    const int c  = warp;
    const int sc = c >> 2;              // swizzle key
    float4 t0[4], t1[4], y[4];
    #pragma unroll
    for (int i = 0; i < 4; ++i)
        t0[i] = *reinterpret_cast<const float4*>(
                    &xn[c * XS + 4 * ((lane + 32 * i) ^ sc)]);

    {
        float4 s[4];
        nbr_sum16(t0, s, lane);
        const float c0 = csm[0], c1 = csm[1];
        #pragma unroll
        for (int i = 0; i < 4; ++i) {
            t1[i] = make_float4(-0.5f * s[i].x, -0.5f * s[i].y,
                                -0.5f * s[i].z, -0.5f * s[i].w);
            y[i]  = make_float4(fmaf(c1, t1[i].x, c0 * t0[i].x),
                                fmaf(c1, t1[i].y, c0 * t0[i].y),
                                fmaf(c1, t1[i].z, c0 * t0[i].z),
                                fmaf(c1, t1[i].w, c0 * t0[i].w));
        }
    }
    cheb_step16(t0, t1, y, csm[2], lane);   // T2
    cheb_step16(t1, t0, y, csm[3], lane);   // T3
    cheb_step16(t0, t1, y, csm[4], lane);   // T4
    cheb_step16(t1, t0, y, csm[5], lane);   // T5
    cheb_step16(t0, t1, y, csm[6], lane);   // T6
    cheb_step16(t1, t0, y, csm[7], lane);   // T7
    cheb_step16(t0, t1, y, csm[8], lane);   // T8

    #pragma unroll
    for (int i = 0; i < 4; ++i)
        *reinterpret_cast<float4*>(
            &xn[c * XS + 4 * ((lane + 32 * i) ^ sc)]) = y[i];
    __syncthreads();

    // ---------------- Phase C: z = M_g * y ; lane = out channel ------------
    float Mreg[DG];
    #pragma unroll
    for (int k = 0; k < DG; ++k)
        Mreg[k] = Msm[lane * MS + k];   // conflict-free scalar

    #pragma unroll
    for (int tb = 0; tb < 4; ++tb) {
        const int w0 = wb + tb * 4;     // l = warp, j4 = tb
        float zx = 0.f, zy = 0.f, zz = 0.f, zw = 0.f;
        #pragma unroll
        for (int k = 0; k < DG; ++k) {
            // uniform address -> broadcast LDS.128 serving 4 tokens
            float4 yv = *reinterpret_cast<const float4*>(
                            &xn[k * XS + 4 * ((warp + 32 * tb) ^ (k >> 2))]);
            zx = fmaf(Mreg[k], yv.x, zx);
            zy = fmaf(Mreg[k], yv.y, zy);
            zz = fmaf(Mreg[k], yv.z, zz);
            zw = fmaf(Mreg[k], yv.w, zw);
        }
        float* o = &out[base + (size_t)w0 * D_DIM + lane];
        o[0 * D_DIM] = zx;
        o[1 * D_DIM] = zy;
        o[2 * D_DIM] = zz;
        o[3 * D_DIM] = zw;
    }
}

// ---------------------------------------------------------------------------
extern "C" void kernel_launch(void* const* d_in, const int* in_sizes, int n_in,
                              void* d_out, int out_size) {
    const float* x    = (const float*)d_in[0];
    const float* cheb = (const float*)d_in[1];
    const float* U    = (const float*)d_in[2];
    const float* V    = (const float*)d_in[3];
    const float* S    = (const float*)d_in[4];
    float* out = (float*)d_out;

    const int B = in_sizes[0] / (W_DIM * D_DIM);

    const size_t smem = (DG * XS + DG * MS + 16) * sizeof(float);  // ~70.4 KB
    cudaFuncSetAttribute(continuous_block_kernel,
                         cudaFuncAttributeMaxDynamicSharedMemorySize, (int)smem);

    precompute_M_kernel<<<GROUPS, 1024>>>(U, V, S);
    continuous_block_kernel<<<B * GROUPS, 1024, smem>>>(x, cheb, out);
}

// round 8
// speedup vs baseline: 2.9014x; 1.2308x over previous
#include <cuda_runtime.h>
#include <cuda_bf16.h>
#include <math.h>

// Problem constants (fixed by the reference)
#define GROUPS 8
#define DG     32        // D / GROUPS
#define W_DIM  512
#define D_DIM  256
#define KCOEF  9         // CHEB_DEG + 1
#define RANK   16
#define DT_C   0.1f
#define XS     516       // xn row stride in floats (XS mod 32 == 4)
#define MS     33        // M row stride (scalar access, conflict-free)
#define FULL   0xffffffffu
#define NTHR   512       // 16 warps; 2 blocks/SM (64 regs * 512 * 2 = full RF)

// Slab layout:  addr(c, w) = c*XS + 4*((l + 32*j4) ^ (c>>2)) + (w&3)
//   where l = w>>4 (owning lane in Phase B), j4 = (w>>2)&3.
// Conflict-free for: Phase A transposed scalar stores, Phase B per-lane
// contiguous float4 loads/stores, Phase C uniform broadcast reads.

// Precomputed per-group integration matrix M_g = (I + dt A + 0.5 dt^2 A^2)^4
__device__ float d_M[GROUPS * DG * DG];

// ---------------------------------------------------------------------------
// Precompute kernel: one block per group, 1024 threads (i = tid>>5, j = tid&31)
// ---------------------------------------------------------------------------
__global__ void precompute_M_kernel(const float* __restrict__ U,
                                    const float* __restrict__ V,
                                    const float* __restrict__ S) {
    const int g   = blockIdx.x;
    const int tid = threadIdx.x;
    const int i   = tid >> 5;
    const int j   = tid & 31;

    __shared__ float Us[DG * RANK], Vs[DG * RANK], Ss[DG * RANK];
    __shared__ float A[DG * 33], P[DG * 33], Q[DG * 33];
    __shared__ float trR_sh;

    if (tid < DG * RANK) {
        Us[tid] = U[g * DG * RANK + tid];
        Vs[tid] = V[g * DG * RANK + tid];
        Ss[tid] = S[g * DG * RANK + tid];
    }
    __syncthreads();

    if (tid < 32) {
        float s = 0.f;
        #pragma unroll
        for (int r = 0; r < RANK; ++r) {
            float v = Ss[tid * RANK + r];
            s = fmaf(v, v, s);
        }
        #pragma unroll
        for (int off = 16; off; off >>= 1)
            s += __shfl_xor_sync(FULL, s, off);
        if (tid == 0) trR_sh = s;
    }
    __syncthreads();

    {
        float a = 0.f;
        #pragma unroll
        for (int r = 0; r < RANK; ++r) {
            a = fmaf(Us[i * RANK + r],  Vs[j * RANK + r], a);
            a = fmaf(-Vs[i * RANK + r], Us[j * RANK + r], a);
            a = fmaf(-Ss[i * RANK + r], Ss[j * RANK + r], a);
        }
        if (i == j) a += trR_sh / (float)DG;
        A[i * 33 + j] = a;
    }
    __syncthreads();

    {
        float a2 = 0.f;
        #pragma unroll
        for (int k = 0; k < DG; ++k)
            a2 = fmaf(A[i * 33 + k], A[k * 33 + j], a2);
        float p = DT_C * A[i * 33 + j] + 0.5f * DT_C * DT_C * a2;
        if (i == j) p += 1.0f;
        P[i * 33 + j] = p;
    }
    __syncthreads();

    {
        float q = 0.f;
        #pragma unroll
        for (int k = 0; k < DG; ++k)
            q = fmaf(P[i * 33 + k], P[k * 33 + j], q);
        Q[i * 33 + j] = q;
    }
    __syncthreads();

    {
        float m = 0.f;
        #pragma unroll
        for (int k = 0; k < DG; ++k)
            m = fmaf(Q[i * 33 + k], Q[k * 33 + j], m);
        d_M[g * DG * DG + i * DG + j] = m;
    }
}

// ---------------------------------------------------------------------------
// float4 helpers
// ---------------------------------------------------------------------------
__device__ __forceinline__ float4 f4_fma(float a, const float4 v, const float4 acc) {
    return make_float4(fmaf(a, v.x, acc.x), fmaf(a, v.y, acc.y),
                       fmaf(a, v.z, acc.z), fmaf(a, v.w, acc.w));
}
__device__ __forceinline__ float4 f4_negsub(const float4 s, const float4 t) {
    return make_float4(-s.x - t.x, -s.y - t.y, -s.z - t.z, -s.w - t.w);
}

// Neighbor sums for the path-Laplacian stencil. Each lane holds 16 CONTIGUOUS
// tokens w = 16*lane + j (t[4] float4s). Only 2 shuffles per application;
// Dirichlet zeros at w=0 and w=511.
__device__ __forceinline__ void nbr_sum16(const float4 (&t)[4], float4 (&s)[4], int lane) {
    float tl = __shfl_sync(FULL, t[3].w, (lane + 31) & 31);  // lane-1's last
    float tr = __shfl_sync(FULL, t[0].x, (lane + 1) & 31);   // lane+1's first
    if (lane == 0)  tl = 0.f;
    if (lane == 31) tr = 0.f;
    #pragma unroll
    for (int i = 0; i < 4; ++i) {
        s[i].x = (i > 0 ? t[i - 1].w : tl) + t[i].y;
        s[i].y = t[i].x + t[i].z;
        s[i].z = t[i].y + t[i].w;
        s[i].w = t[i].z + (i < 3 ? t[i + 1].x : tr);
    }
}

// One Chebyshev recurrence step: tp := -(left+right)(tc) - tp ;  y += ck*tp
__device__ __forceinline__ void cheb_step16(float4 (&tp)[4], const float4 (&tc)[4],
                                            float4 (&y)[4], float ck, int lane) {
    float4 s[4];
    nbr_sum16(tc, s, lane);
    #pragma unroll
    for (int i = 0; i < 4; ++i) {
        tp[i] = f4_negsub(s[i], tp[i]);
        y[i]  = f4_fma(ck, tp[i], y[i]);
    }
}

// ---------------------------------------------------------------------------
// Fused kernel: norm -> Chebyshev -> matvec(M_g).  Block = (b, g), 512 thr.
// 2 blocks resident per SM so one block's L1-heavy phases (A/C) overlap the
// other's shuffle/FMA phase (B).
// ---------------------------------------------------------------------------
__global__ __launch_bounds__(NTHR, 2)
void continuous_block_kernel(const float* __restrict__ x,
                             const float* __restrict__ cheb,
                             float* __restrict__ out) {
    extern __shared__ float sm[];
    float* xn  = sm;                    // [32][XS] channel-major swizzled slab
    float* Msm = sm + DG * XS;          // [32][MS]
    float* csm = Msm + DG * MS;         // [KCOEF]

    const int g    = blockIdx.x & (GROUPS - 1);
    const int b    = blockIdx.x >> 3;
    const int tid  = threadIdx.x;
    const int warp = tid >> 5;          // 0..15
    const int lane = tid & 31;

    // Stage M (16 warps cover 32 rows) and cheb coefs
    Msm[warp * MS + lane]        = d_M[g * DG * DG + warp * DG + lane];
    Msm[(warp + 16) * MS + lane] = d_M[g * DG * DG + (warp + 16) * DG + lane];
    if (tid < KCOEF) csm[tid] = cheb[g * KCOEF + tid];

    const size_t base = ((size_t)b * W_DIM) * D_DIM + (size_t)g * DG;

    // ---------------- Phase A: load + groupwise norm ------------------------
    // lane = 8*tg + c4 : tg = token-in-quad (w&3), c4 = channel quad.
    // Each warp handles two 16-token segments (warp2 = warp, warp+16).
    {
        const int tg = lane >> 3;
        const int c4 = lane & 7;
        #pragma unroll 1
        for (int ws = 0; ws < 2; ++ws) {
            const int warp2 = warp + 16 * ws;
            const int wb    = warp2 * 16;
            float4 v[4];
            #pragma unroll
            for (int tb = 0; tb < 4; ++tb) {
                const int w = wb + tb * 4 + tg;
                v[tb] = *reinterpret_cast<const float4*>(
                            &x[base + (size_t)w * D_DIM + c4 * 4]);
            }
            #pragma unroll
            for (int tb = 0; tb < 4; ++tb) {
                float s  = v[tb].x + v[tb].y + v[tb].z + v[tb].w;
                float s2 = fmaf(v[tb].x, v[tb].x, fmaf(v[tb].y, v[tb].y,
                           fmaf(v[tb].z, v[tb].z, v[tb].w * v[tb].w)));
                #pragma unroll
                for (int off = 4; off; off >>= 1) {   // within 8-lane group
                    s  += __shfl_xor_sync(FULL, s,  off);
                    s2 += __shfl_xor_sync(FULL, s2, off);
                }
                const float mu  = s * (1.0f / DG);
                const float var = fmaf(s2, 1.0f / DG, -mu * mu);
                const float inv = rsqrtf(var + 1e-6f);
                const float nx = (v[tb].x - mu) * inv;
                const float ny = (v[tb].y - mu) * inv;
                const float nz = (v[tb].z - mu) * inv;
                const float nw = (v[tb].w - mu) * inv;
                // slot = (l + 32*j4) ^ (c>>2): l = warp2, j4 = tb, c>>2 = c4
                const int off4 = 4 * ((warp2 + 32 * tb) ^ c4) + tg;
                xn[(4 * c4 + 0) * XS + off4] = nx;
                xn[(4 * c4 + 1) * XS + off4] = ny;
                xn[(4 * c4 + 2) * XS + off4] = nz;
                xn[(4 * c4 + 3) * XS + off4] = nw;
            }
        }
    }
    __syncthreads();

    // ---------------- Phase B: Chebyshev along W (2 sequential channels) ----
    // Lane holds 16 contiguous tokens w = 16*lane .. 16*lane+15.
    #pragma unroll 1
    for (int cp = 0; cp < 2; ++cp) {
        const int c  = warp + 16 * cp;
        const int sc = c >> 2;          // swizzle key
        float4 t0[4], t1[4], y[4];
        #pragma unroll
        for (int i = 0; i < 4; ++i)
            t0[i] = *reinterpret_cast<const float4*>(
                        &xn[c * XS + 4 * ((lane + 32 * i) ^ sc)]);

        {
            float4 s[4];
            nbr_sum16(t0, s, lane);
            const float c0 = csm[0], c1 = csm[1];
            #pragma unroll
            for (int i = 0; i < 4; ++i) {
                t1[i] = make_float4(-0.5f * s[i].x, -0.5f * s[i].y,
                                    -0.5f * s[i].z, -0.5f * s[i].w);
                y[i]  = make_float4(fmaf(c1, t1[i].x, c0 * t0[i].x),
                                    fmaf(c1, t1[i].y, c0 * t0[i].y),
                                    fmaf(c1, t1[i].z, c0 * t0[i].z),
                                    fmaf(c1, t1[i].w, c0 * t0[i].w));
            }
        }
        cheb_step16(t0, t1, y, csm[2], lane);   // T2
        cheb_step16(t1, t0, y, csm[3], lane);   // T3
        cheb_step16(t0, t1, y, csm[4], lane);   // T4
        cheb_step16(t1, t0, y, csm[5], lane);   // T5
        cheb_step16(t0, t1, y, csm[6], lane);   // T6
        cheb_step16(t1, t0, y, csm[7], lane);   // T7
        cheb_step16(t0, t1, y, csm[8], lane);   // T8

        #pragma unroll
        for (int i = 0; i < 4; ++i)
            *reinterpret_cast<float4*>(
                &xn[c * XS + 4 * ((lane + 32 * i) ^ sc)]) = y[i];
    }
    __syncthreads();

    // ---------------- Phase C: z = M_g * y ; lane = out channel ------------
    float Mreg[DG];
    #pragma unroll
    for (int k = 0; k < DG; ++k)
        Mreg[k] = Msm[lane * MS + k];   // conflict-free scalar

    #pragma unroll 1
    for (int ws = 0; ws < 2; ++ws) {
        const int warp2 = warp + 16 * ws;
        const int wb    = warp2 * 16;
        #pragma unroll
        for (int tb = 0; tb < 4; ++tb) {
            const int w0 = wb + tb * 4;     // l = warp2, j4 = tb
            float zx = 0.f, zy = 0.f, zz = 0.f, zw = 0.f;
            #pragma unroll
            for (int k = 0; k < DG; ++k) {
                // uniform address -> broadcast LDS.128 serving 4 tokens
                float4 yv = *reinterpret_cast<const float4*>(
                                &xn[k * XS + 4 * ((warp2 + 32 * tb) ^ (k >> 2))]);
                zx = fmaf(Mreg[k], yv.x, zx);
                zy = fmaf(Mreg[k], yv.y, zy);
                zz = fmaf(Mreg[k], yv.z, zz);
                zw = fmaf(Mreg[k], yv.w, zw);
            }
            float* o = &out[base + (size_t)w0 * D_DIM + lane];
            o[0 * D_DIM] = zx;
            o[1 * D_DIM] = zy;
            o[2 * D_DIM] = zz;
            o[3 * D_DIM] = zw;
        }
    }
}

// ---------------------------------------------------------------------------
extern "C" void kernel_launch(void* const* d_in, const int* in_sizes, int n_in,
                              void* d_out, int out_size) {
    const float* x    = (const float*)d_in[0];
    const float* cheb = (const float*)d_in[1];
    const float* U    = (const float*)d_in[2];
    const float* V    = (const float*)d_in[3];
    const float* S    = (const float*)d_in[4];
    float* out = (float*)d_out;

    const int B = in_sizes[0] / (W_DIM * D_DIM);

    const size_t smem = (DG * XS + DG * MS + 16) * sizeof(float);  // ~70.4 KB
    cudaFuncSetAttribute(continuous_block_kernel,
                         cudaFuncAttributeMaxDynamicSharedMemorySize, (int)smem);

    precompute_M_kernel<<<GROUPS, 1024>>>(U, V, S);
    continuous_block_kernel<<<B * GROUPS, NTHR, smem>>>(x, cheb, out);
}